// round 1
// baseline (speedup 1.0000x reference)
#include <cuda_runtime.h>
#include <cuda_bf16.h>
#include <math.h>
#include <string.h>

// ---------------------------------------------------------------------------
// Constants of the problem
//   H=16, D=128, d=2048, N_BASIS=1024, MEM_LEN=l=512, QLEN=2048, RIDGE=0.5
//   b_mu[n]   = linspace(0,1,512)[n/2]
//   b_sigma[n]= (n&1) ? 0.01 : 0.005
// ---------------------------------------------------------------------------

// ------------------------- device scratch (static) -------------------------
__device__ float g_G2 [1024 * 512];          //  2 MB : G2[n][l] = G[l][n]
__device__ float g_KVt[4096 * 512];          //  8 MB : KVt[j][l] = sum_d W[j,d]*k[l,d]
__device__ float g_KV2[1024 * 4096];         // 16 MB : KV2[n][j] = keys|values
__device__ float g_S  [16 * 2048 * 1024];    //134 MB : scores, overwritten by r
__device__ float g_ctx[2048 * 2048];         // 16 MB : context

// ------------------------- host-side G2 computation ------------------------
static double hF[1024 * 1024];
static double hA[1024 * 1024];
static double hX[1024 * 1024];
static float  hG2[1024 * 512];
static double hbmu[1024], hbsig[1024];
static int    hlo[1024], hhi[1024];

static void compute_G2_host()
{
    const int n = 1024, P = 1024;   // P = 2*l
    for (int i = 0; i < 512; i++) {
        double m = (double)i / 511.0;
        hbmu[2*i] = m;  hbmu[2*i+1] = m;
        hbsig[2*i] = 0.005; hbsig[2*i+1] = 0.01;
    }
    const double shift = 1.0 / 1024.0;
    const double start = -0.5 + shift, stop = 1.5 - shift;
    const double step  = (stop - start) / (double)(P - 1);
    const double inv_sqrt2pi = 0.39894228040143267794;

    // F[b][p] = pdf(pos[p]; mu_b, sig_b); track nonzero support per row
    for (int b = 0; b < n; b++) {
        double mu = hbmu[b], sg = hbsig[b];
        double c = inv_sqrt2pi / sg;
        int lo = P, hi = 0;
        for (int p = 0; p < P; p++) {
            double x = start + p * step;
            double t = (x - mu) / sg;
            double v = (fabs(t) < 38.0) ? c * exp(-0.5 * t * t) : 0.0;
            hF[(long)b * P + p] = v;
            if (v != 0.0) { if (p < lo) lo = p; if (p + 1 > hi) hi = p + 1; }
        }
        hlo[b] = lo; hhi[b] = hi;
    }

    // A = F F^T + 0.5 I  (use support overlap; exact zeros elsewhere)
    memset(hA, 0, sizeof(hA));
    for (int i = 0; i < n; i++) {
        for (int j = i; j < n; j++) {
            int lo = hlo[i] > hlo[j] ? hlo[i] : hlo[j];
            int hi = hhi[i] < hhi[j] ? hhi[i] : hhi[j];
            double s = 0.0;
            if (lo < hi) {
                const double* fi = &hF[(long)i * P];
                const double* fj = &hF[(long)j * P];
                for (int p = lo; p < hi; p++) s += fi[p] * fj[p];
            }
            if (i == j) s += 0.5;
            hA[(long)i * n + j] = s;
            hA[(long)j * n + i] = s;
        }
    }

    // Cholesky (lower), row-oriented, in place
    for (int i = 0; i < n; i++) {
        for (int j = 0; j <= i; j++) {
            double s = hA[(long)i * n + j];
            const double* Li = &hA[(long)i * n];
            const double* Lj = &hA[(long)j * n];
            for (int k2 = 0; k2 < j; k2++) s -= Li[k2] * Lj[k2];
            if (j == i) hA[(long)i * n + i] = sqrt(s);
            else        hA[(long)i * n + j] = s / hA[(long)j * n + j];
        }
    }

    // X := F ; forward solve L X = F  (row ops, skip exact zeros in band)
    memcpy(hX, hF, sizeof(hX));
    for (int i = 0; i < n; i++) {
        double* xi = &hX[(long)i * P];
        const double* Li = &hA[(long)i * n];
        for (int k2 = 0; k2 < i; k2++) {
            double l = Li[k2];
            if (l != 0.0) {
                const double* xk = &hX[(long)k2 * P];
                for (int p = 0; p < P; p++) xi[p] -= l * xk[p];
            }
        }
        double inv = 1.0 / hA[(long)i * n + i];
        for (int p = 0; p < P; p++) xi[p] *= inv;
    }
    // back solve L^T X = Y
    for (int i = n - 1; i >= 0; i--) {
        double* xi = &hX[(long)i * P];
        for (int k2 = i + 1; k2 < n; k2++) {
            double l = hA[(long)k2 * n + i];
            if (l != 0.0) {
                const double* xk = &hX[(long)k2 * P];
                for (int p = 0; p < P; p++) xi[p] -= l * xk[p];
            }
        }
        double inv = 1.0 / hA[(long)i * n + i];
        for (int p = 0; p < P; p++) xi[p] *= inv;
    }

    // G2[b][l] = X[b][l+256]
    for (int b = 0; b < n; b++)
        for (int l = 0; l < 512; l++)
            hG2[b * 512 + l] = (float)hX[(long)b * P + 256 + l];
}

// ------------------------- device kernels ----------------------------------

// Copy the host-resident G2 table into device memory each replay (ATS read
// over NVLink-C2C; ~2MB -> ~10us). Kernel-only, so trivially capturable.
__global__ void copy_g2_kernel(const float4* __restrict__ src, float4* __restrict__ dst, int n4)
{
    int i = blockIdx.x * blockDim.x + threadIdx.x;
    if (i < n4) dst[i] = src[i];
}

// Tiled fp32 GEMM: C[m][n] = alpha * sum_k A[m][k] * (BT ? B[n][k] : B[k][n])
// 128x128 block tile, BK=16, 256 threads, 8x8 per thread, batched via z.
// Requires: M%128==0, N%128==0, K%16==0, all pointers/lds 16B aligned.
template<bool BT>
__global__ __launch_bounds__(256)
void gemm128(const float* __restrict__ Ab, int lda, long long sA,
             const float* __restrict__ Bb, int ldb, long long sB,
             float*       __restrict__ Cb, int ldc, long long sC,
             int K, float alpha)
{
    constexpr int BM = 128, BN = 128, BK = 16;
    __shared__ float As[BK][BM + 4];
    __shared__ float Bs[BK][BN + 4];

    const int tid = threadIdx.x;
    const int tx = tid & 15, ty = tid >> 4;

    const float* A = Ab + (long long)blockIdx.z * sA + (long long)blockIdx.y * BM * lda;
    const float* B = Bb + (long long)blockIdx.z * sB
                        + (BT ? (long long)blockIdx.x * BN * ldb
                              : (long long)blockIdx.x * BN);
    float* C = Cb + (long long)blockIdx.z * sC
                  + (long long)blockIdx.y * BM * ldc + (long long)blockIdx.x * BN;

    float acc[8][8];
    #pragma unroll
    for (int i = 0; i < 8; i++)
        #pragma unroll
        for (int j = 0; j < 8; j++) acc[i][j] = 0.f;

    for (int k0 = 0; k0 < K; k0 += BK) {
        // A tile (128 rows x 16 k), store transposed As[k][m]
        #pragma unroll
        for (int p = 0; p < 2; p++) {
            int f   = tid + p * 256;
            int row = f >> 2;
            int c4  = (f & 3) << 2;
            float4 v = *reinterpret_cast<const float4*>(A + (long long)row * lda + k0 + c4);
            As[c4 + 0][row] = v.x; As[c4 + 1][row] = v.y;
            As[c4 + 2][row] = v.z; As[c4 + 3][row] = v.w;
        }
        if (BT) {
            // B tile (128 n-rows x 16 k), store transposed Bs[k][n]
            #pragma unroll
            for (int p = 0; p < 2; p++) {
                int f   = tid + p * 256;
                int row = f >> 2;
                int c4  = (f & 3) << 2;
                float4 v = *reinterpret_cast<const float4*>(B + (long long)row * ldb + k0 + c4);
                Bs[c4 + 0][row] = v.x; Bs[c4 + 1][row] = v.y;
                Bs[c4 + 2][row] = v.z; Bs[c4 + 3][row] = v.w;
            }
        } else {
            // B tile (16 k-rows x 128 n), direct Bs[k][n]
            #pragma unroll
            for (int p = 0; p < 2; p++) {
                int f   = tid + p * 256;
                int row = f >> 5;
                int c4  = (f & 31) << 2;
                float4 v = *reinterpret_cast<const float4*>(B + (long long)(k0 + row) * ldb + c4);
                *reinterpret_cast<float4*>(&Bs[row][c4]) = v;
            }
        }
        __syncthreads();

        #pragma unroll
        for (int kk = 0; kk < BK; kk++) {
            float a[8], b[8];
            #pragma unroll
            for (int i = 0; i < 8; i++) a[i] = As[kk][ty * 8 + i];
            #pragma unroll
            for (int j = 0; j < 8; j++) b[j] = Bs[kk][tx * 8 + j];
            #pragma unroll
            for (int i = 0; i < 8; i++)
                #pragma unroll
                for (int j = 0; j < 8; j++) acc[i][j] += a[i] * b[j];
        }
        __syncthreads();
    }

    #pragma unroll
    for (int i = 0; i < 8; i++) {
        #pragma unroll
        for (int j4 = 0; j4 < 2; j4++) {
            float4 v;
            v.x = alpha * acc[i][j4 * 4 + 0];
            v.y = alpha * acc[i][j4 * 4 + 1];
            v.z = alpha * acc[i][j4 * 4 + 2];
            v.w = alpha * acc[i][j4 * 4 + 3];
            *reinterpret_cast<float4*>(C + (long long)(ty * 8 + i) * ldc + tx * 8 + j4 * 4) = v;
        }
    }
}

// Per (h,q) row: mu = sigmoid(s.w_mu), var = max(softplus(s.w_sigma),1e-4),
// then overwrite the row with r[n] = pdf(b_mu[n]; mu, sqrt(var+b_sig[n]^2)).
__global__ __launch_bounds__(256)
void row_r_kernel(float* __restrict__ S,
                  const float* __restrict__ wmu,
                  const float* __restrict__ wsg)
{
    long long row = blockIdx.x;                 // h*2048 + q   (32768 rows)
    float* s = S + row * 1024;
    int t = threadIdx.x;

    float pm = 0.f, ps = 0.f;
    #pragma unroll
    for (int i = 0; i < 4; i++) {
        int idx = t + i * 256;
        float v = s[idx];
        pm += v * wmu[idx];
        ps += v * wsg[idx];
    }
    #pragma unroll
    for (int o = 16; o > 0; o >>= 1) {
        pm += __shfl_down_sync(0xffffffffu, pm, o);
        ps += __shfl_down_sync(0xffffffffu, ps, o);
    }
    __shared__ float rm[8], rs[8];
    __shared__ float bc[5];
    int w = t >> 5, lane = t & 31;
    if (lane == 0) { rm[w] = pm; rs[w] = ps; }
    __syncthreads();
    if (t == 0) {
        float m = 0.f, g = 0.f;
        #pragma unroll
        for (int i = 0; i < 8; i++) { m += rm[i]; g += rs[i]; }
        float mu  = 1.f / (1.f + __expf(-m));
        float sp  = (g > 20.f) ? g : log1pf(__expf(g));
        float var = fmaxf(sp, 1e-4f);
        float sv0 = var + 2.5e-5f;   // b_sigma = 0.005
        float sv1 = var + 1.0e-4f;   // b_sigma = 0.01
        bc[0] = mu;
        bc[1] = rsqrtf(6.28318530717958648f * sv0);
        bc[2] = -0.5f / sv0;
        bc[3] = rsqrtf(6.28318530717958648f * sv1);
        bc[4] = -0.5f / sv1;
    }
    __syncthreads();
    float mu = bc[0], c0 = bc[1], h0 = bc[2], c1 = bc[3], h1 = bc[4];
    #pragma unroll
    for (int i = 0; i < 4; i++) {
        int idx = t + i * 256;
        float bmu = (float)(idx >> 1) * (1.0f / 511.0f);
        float d = bmu - mu;
        float c = (idx & 1) ? c1 : c0;
        float h = (idx & 1) ? h1 : h0;
        s[idx] = c * __expf(h * d * d);
    }
}

// ------------------------- launch ------------------------------------------
extern "C" void kernel_launch(void* const* d_in, const int* in_sizes, int n_in,
                              void* d_out, int out_size)
{
    (void)in_sizes; (void)n_in; (void)out_size;
    const float* dk   = (const float*)d_in[0];   // (1,512,2048)
    const float* dq   = (const float*)d_in[1];   // (1,16,2048,128)
    const float* dWk  = (const float*)d_in[2];   // (2048,2048)
    const float* dWv  = (const float*)d_in[3];   // (2048,2048)
    const float* dWo  = (const float*)d_in[4];   // (2048,2048)
    const float* dwmu = (const float*)d_in[5];   // (1024,)
    const float* dwsg = (const float*)d_in[6];   // (1024,)
    float* dout = (float*)d_out;                 // (1,2048,2048)

    // Input-independent constants: computed on host (fp64), not in the graph.
    compute_G2_host();

    float *pG2, *pKVt, *pKV2, *pS, *pCtx;
    cudaGetSymbolAddress((void**)&pG2,  g_G2);
    cudaGetSymbolAddress((void**)&pKVt, g_KVt);
    cudaGetSymbolAddress((void**)&pKV2, g_KV2);
    cudaGetSymbolAddress((void**)&pS,   g_S);
    cudaGetSymbolAddress((void**)&pCtx, g_ctx);

    // 0: bring G2 on-device (ATS read of static host array; graph-capturable)
    {
        int n4 = (1024 * 512) / 4;
        copy_g2_kernel<<<(n4 + 255) / 256, 256>>>(
            reinterpret_cast<const float4*>(hG2),
            reinterpret_cast<float4*>(pG2), n4);
    }

    // 1: KVt[z*2048 + j][l] = sum_d W[j,d] * k[l,d]   (z=0:W_key, z=1:W_val)
    {
        long long sA = (long long)(dWv - dWk);   // batch over the two weights
        dim3 g(512 / 128, 2048 / 128, 2);
        gemm128<true><<<g, 256>>>(dWk, 2048, sA,
                                  dk,  2048, 0,
                                  pKVt, 512, 2048LL * 512,
                                  2048, 1.0f);
    }
    // 2: KV2[n][j] = sum_l G2[n][l] * KVt[j][l]
    {
        dim3 g(4096 / 128, 1024 / 128, 1);
        gemm128<true><<<g, 256>>>(pG2, 512, 0,
                                  pKVt, 512, 0,
                                  pKV2, 4096, 0,
                                  512, 1.0f);
    }
    // 3: scores[h][q][n] = (1/sqrt(128)) * sum_d q[h,q,d] * keys[n, h*128+d]
    {
        dim3 g(1024 / 128, 2048 / 128, 16);
        gemm128<true><<<g, 256>>>(dq, 128, 2048LL * 128,
                                  pKV2, 4096, 128,
                                  pS, 1024, 2048LL * 1024,
                                  128, 0.08838834764831845f);
    }
    // 4: mu/sigma reduction + r (in place over scores)
    row_r_kernel<<<16 * 2048, 256>>>(pS, dwmu, dwsg);

    // 5: ctx[q][h*128+d] = sum_n r[h,q,n] * values[n, h*128+d]
    {
        dim3 g(1, 2048 / 128, 16);
        gemm128<false><<<g, 256>>>(pS, 1024, 2048LL * 1024,
                                   pKV2 + 2048, 4096, 128,
                                   pCtx, 2048, 128,
                                   1024, 1.0f);
    }
    // 6: out[q][o] = sum_c ctx[q][c] * W_out[o][c]
    {
        dim3 g(2048 / 128, 2048 / 128, 1);
        gemm128<true><<<g, 256>>>(pCtx, 2048, 0,
                                  dWo, 2048, 0,
                                  dout, 2048, 0,
                                  2048, 1.0f);
    }
}

// round 2
// speedup vs baseline: 1.2909x; 1.2909x over previous
#include <cuda_runtime.h>
#include <cuda_bf16.h>
#include <math.h>
#include <string.h>

// ---------------------------------------------------------------------------
// Constants of the problem
//   H=16, D=128, d=2048, N_BASIS=1024, MEM_LEN=l=512, QLEN=2048, RIDGE=0.5
// ---------------------------------------------------------------------------

typedef unsigned long long ull;

// ------------------------- device scratch (static) -------------------------
__device__ float g_G2 [1024 * 512];          //  2 MB : G2[n][l] = G[l][n]
__device__ float g_KVt[4096 * 512];          //  8 MB : KVt[j][l]
__device__ float g_KV2[1024 * 4096];         // 16 MB : KV2[n][j] = keys|values
__device__ float g_S  [16 * 2048 * 1024];    //134 MB : scores -> r (in place)
__device__ float g_ctx[2048 * 2048];         // 16 MB : context

// ------------------------- host-side G2 computation ------------------------
static double hF[1024 * 1024];
static double hA[1024 * 1024];
static double hX[1024 * 1024];
static float  hG2[1024 * 512];
static double hbmu[1024], hbsig[1024];
static int    hlo[1024], hhi[1024];

static void compute_G2_host()
{
    const int n = 1024, P = 1024;
    for (int i = 0; i < 512; i++) {
        double m = (double)i / 511.0;
        hbmu[2*i] = m;  hbmu[2*i+1] = m;
        hbsig[2*i] = 0.005; hbsig[2*i+1] = 0.01;
    }
    const double shift = 1.0 / 1024.0;
    const double start = -0.5 + shift, stop = 1.5 - shift;
    const double step  = (stop - start) / (double)(P - 1);
    const double inv_sqrt2pi = 0.39894228040143267794;

    for (int b = 0; b < n; b++) {
        double mu = hbmu[b], sg = hbsig[b];
        double c = inv_sqrt2pi / sg;
        int lo = P, hi = 0;
        for (int p = 0; p < P; p++) {
            double x = start + p * step;
            double t = (x - mu) / sg;
            double v = (fabs(t) < 38.0) ? c * exp(-0.5 * t * t) : 0.0;
            hF[(long)b * P + p] = v;
            if (v != 0.0) { if (p < lo) lo = p; if (p + 1 > hi) hi = p + 1; }
        }
        hlo[b] = lo; hhi[b] = hi;
    }

    memset(hA, 0, sizeof(hA));
    for (int i = 0; i < n; i++) {
        for (int j = i; j < n; j++) {
            int lo = hlo[i] > hlo[j] ? hlo[i] : hlo[j];
            int hi = hhi[i] < hhi[j] ? hhi[i] : hhi[j];
            double s = 0.0;
            if (lo < hi) {
                const double* fi = &hF[(long)i * P];
                const double* fj = &hF[(long)j * P];
                for (int p = lo; p < hi; p++) s += fi[p] * fj[p];
            }
            if (i == j) s += 0.5;
            hA[(long)i * n + j] = s;
            hA[(long)j * n + i] = s;
        }
    }

    // Cholesky (lower), in place
    for (int i = 0; i < n; i++) {
        for (int j = 0; j <= i; j++) {
            double s = hA[(long)i * n + j];
            const double* Li = &hA[(long)i * n];
            const double* Lj = &hA[(long)j * n];
            for (int k2 = 0; k2 < j; k2++) s -= Li[k2] * Lj[k2];
            if (j == i) hA[(long)i * n + i] = sqrt(s);
            else        hA[(long)i * n + j] = s / hA[(long)j * n + j];
        }
    }

    memcpy(hX, hF, sizeof(hX));
    for (int i = 0; i < n; i++) {
        double* xi = &hX[(long)i * P];
        const double* Li = &hA[(long)i * n];
        for (int k2 = 0; k2 < i; k2++) {
            double l = Li[k2];
            if (l != 0.0) {
                const double* xk = &hX[(long)k2 * P];
                for (int p = 0; p < P; p++) xi[p] -= l * xk[p];
            }
        }
        double inv = 1.0 / hA[(long)i * n + i];
        for (int p = 0; p < P; p++) xi[p] *= inv;
    }
    for (int i = n - 1; i >= 0; i--) {
        double* xi = &hX[(long)i * P];
        for (int k2 = i + 1; k2 < n; k2++) {
            double l = hA[(long)k2 * n + i];
            if (l != 0.0) {
                const double* xk = &hX[(long)k2 * P];
                for (int p = 0; p < P; p++) xi[p] -= l * xk[p];
            }
        }
        double inv = 1.0 / hA[(long)i * n + i];
        for (int p = 0; p < P; p++) xi[p] *= inv;
    }

    for (int b = 0; b < n; b++)
        for (int l = 0; l < 512; l++)
            hG2[b * 512 + l] = (float)hX[(long)b * P + 256 + l];
}

// ------------------------- f32x2 helpers -----------------------------------
__device__ __forceinline__ ull pack2(float lo, float hi) {
    ull r; asm("mov.b64 %0, {%1,%2};" : "=l"(r) : "f"(lo), "f"(hi)); return r;
}
__device__ __forceinline__ void unpack2(ull v, float& lo, float& hi) {
    asm("mov.b64 {%0,%1}, %2;" : "=f"(lo), "=f"(hi) : "l"(v));
}
__device__ __forceinline__ void ffma2(ull& d, ull a, ull b) {
    asm("fma.rn.f32x2 %0, %1, %2, %0;" : "+l"(d) : "l"(a), "l"(b));
}

// ------------------------- device kernels ----------------------------------
__global__ void copy_g2_kernel(const float4* __restrict__ src, float4* __restrict__ dst, int n4)
{
    int i = blockIdx.x * blockDim.x + threadIdx.x;
    if (i < n4) dst[i] = src[i];
}

// Tiled fp32 GEMM with packed f32x2 FMAs and double-buffered smem.
// C[m][n] = alpha * sum_k A[m][k] * (BT ? B[n][k] : B[k][n])
// 128x128 tile, BK=16, 256 threads, per-thread 8 rows x (4 + 4) cols.
template<bool BT>
__global__ __launch_bounds__(256)
void gemm128(const float* __restrict__ Ab, int lda, long long sA,
             const float* __restrict__ Bb, int ldb, long long sB,
             float*       __restrict__ Cb, int ldc, long long sC,
             int K, float alpha)
{
    constexpr int BM = 128, BN = 128, BK = 16, LDSH = BM + 4;
    __shared__ __align__(16) float As[2][BK][LDSH];
    __shared__ __align__(16) float Bs[2][BK][LDSH];

    const int tid = threadIdx.x;
    const int tx = tid & 15, ty = tid >> 4;

    const float* A = Ab + (long long)blockIdx.z * sA + (long long)blockIdx.y * BM * lda;
    const float* B = Bb + (long long)blockIdx.z * sB
                        + (BT ? (long long)blockIdx.x * BN * ldb
                              : (long long)blockIdx.x * BN);
    float* C = Cb + (long long)blockIdx.z * sC
                  + (long long)blockIdx.y * BM * ldc + (long long)blockIdx.x * BN;

    // global-load index precompute
    const int rA = tid >> 2;           // + 64 for second fragment
    const int cA = (tid & 3) << 2;
    int rB0, cB0, rB1;
    if (BT) { rB0 = tid >> 2;  cB0 = (tid & 3) << 2;  rB1 = rB0 + 64; }
    else    { rB0 = tid >> 5;  cB0 = (tid & 31) << 2; rB1 = rB0 + 8;  }

    float4 ra0, ra1, rb0, rb1;

    auto ldg_tile = [&](int k0) {
        ra0 = *reinterpret_cast<const float4*>(A + (long long)rA * lda + k0 + cA);
        ra1 = *reinterpret_cast<const float4*>(A + (long long)(rA + 64) * lda + k0 + cA);
        if (BT) {
            rb0 = *reinterpret_cast<const float4*>(B + (long long)rB0 * ldb + k0 + cB0);
            rb1 = *reinterpret_cast<const float4*>(B + (long long)rB1 * ldb + k0 + cB0);
        } else {
            rb0 = *reinterpret_cast<const float4*>(B + (long long)(k0 + rB0) * ldb + cB0);
            rb1 = *reinterpret_cast<const float4*>(B + (long long)(k0 + rB1) * ldb + cB0);
        }
    };
    auto sts_tile = [&](int buf) {
        As[buf][cA + 0][rA] = ra0.x; As[buf][cA + 1][rA] = ra0.y;
        As[buf][cA + 2][rA] = ra0.z; As[buf][cA + 3][rA] = ra0.w;
        As[buf][cA + 0][rA + 64] = ra1.x; As[buf][cA + 1][rA + 64] = ra1.y;
        As[buf][cA + 2][rA + 64] = ra1.z; As[buf][cA + 3][rA + 64] = ra1.w;
        if (BT) {
            Bs[buf][cB0 + 0][rB0] = rb0.x; Bs[buf][cB0 + 1][rB0] = rb0.y;
            Bs[buf][cB0 + 2][rB0] = rb0.z; Bs[buf][cB0 + 3][rB0] = rb0.w;
            Bs[buf][cB0 + 0][rB1] = rb1.x; Bs[buf][cB0 + 1][rB1] = rb1.y;
            Bs[buf][cB0 + 2][rB1] = rb1.z; Bs[buf][cB0 + 3][rB1] = rb1.w;
        } else {
            *reinterpret_cast<float4*>(&Bs[buf][rB0][cB0]) = rb0;
            *reinterpret_cast<float4*>(&Bs[buf][rB1][cB0]) = rb1;
        }
    };

    ull acc[8][4];
    #pragma unroll
    for (int i = 0; i < 8; i++)
        #pragma unroll
        for (int j = 0; j < 4; j++) acc[i][j] = pack2(0.f, 0.f);

    ldg_tile(0);
    sts_tile(0);
    __syncthreads();

    const int nk = K >> 4;
    for (int t = 0; t < nk; t++) {
        const int cur = t & 1;
        if (t + 1 < nk) ldg_tile((t + 1) << 4);

        #pragma unroll
        for (int kk = 0; kk < BK; kk++) {
            float4 a0 = *reinterpret_cast<const float4*>(&As[cur][kk][ty * 8]);
            float4 a1 = *reinterpret_cast<const float4*>(&As[cur][kk][ty * 8 + 4]);
            float4 b0 = *reinterpret_cast<const float4*>(&Bs[cur][kk][tx * 4]);
            float4 b1 = *reinterpret_cast<const float4*>(&Bs[cur][kk][64 + tx * 4]);
            ull bv0 = pack2(b0.x, b0.y), bv1 = pack2(b0.z, b0.w);
            ull bv2 = pack2(b1.x, b1.y), bv3 = pack2(b1.z, b1.w);
            float av[8] = {a0.x, a0.y, a0.z, a0.w, a1.x, a1.y, a1.z, a1.w};
            #pragma unroll
            for (int i = 0; i < 8; i++) {
                ull ai = pack2(av[i], av[i]);
                ffma2(acc[i][0], ai, bv0);
                ffma2(acc[i][1], ai, bv1);
                ffma2(acc[i][2], ai, bv2);
                ffma2(acc[i][3], ai, bv3);
            }
        }

        if (t + 1 < nk) sts_tile((t + 1) & 1);
        __syncthreads();
    }

    #pragma unroll
    for (int i = 0; i < 8; i++) {
        float4 v0, v1;
        unpack2(acc[i][0], v0.x, v0.y); unpack2(acc[i][1], v0.z, v0.w);
        unpack2(acc[i][2], v1.x, v1.y); unpack2(acc[i][3], v1.z, v1.w);
        v0.x *= alpha; v0.y *= alpha; v0.z *= alpha; v0.w *= alpha;
        v1.x *= alpha; v1.y *= alpha; v1.z *= alpha; v1.w *= alpha;
        float* crow = C + (long long)(ty * 8 + i) * ldc;
        *reinterpret_cast<float4*>(crow + tx * 4)      = v0;
        *reinterpret_cast<float4*>(crow + 64 + tx * 4) = v1;
    }
}

// Per (h,q) row: mu/sigma reduction, then overwrite with r[n].
__global__ __launch_bounds__(256)
void row_r_kernel(float* __restrict__ S,
                  const float* __restrict__ wmu,
                  const float* __restrict__ wsg)
{
    long long row = blockIdx.x;
    float* s = S + row * 1024;
    int t = threadIdx.x;

    float pm = 0.f, ps = 0.f;
    #pragma unroll
    for (int i = 0; i < 4; i++) {
        int idx = t + i * 256;
        float v = s[idx];
        pm += v * wmu[idx];
        ps += v * wsg[idx];
    }
    #pragma unroll
    for (int o = 16; o > 0; o >>= 1) {
        pm += __shfl_down_sync(0xffffffffu, pm, o);
        ps += __shfl_down_sync(0xffffffffu, ps, o);
    }
    __shared__ float rm[8], rs[8];
    __shared__ float bc[5];
    int w = t >> 5, lane = t & 31;
    if (lane == 0) { rm[w] = pm; rs[w] = ps; }
    __syncthreads();
    if (t == 0) {
        float m = 0.f, g = 0.f;
        #pragma unroll
        for (int i = 0; i < 8; i++) { m += rm[i]; g += rs[i]; }
        float mu  = 1.f / (1.f + __expf(-m));
        float sp  = (g > 20.f) ? g : log1pf(__expf(g));
        float var = fmaxf(sp, 1e-4f);
        float sv0 = var + 2.5e-5f;
        float sv1 = var + 1.0e-4f;
        bc[0] = mu;
        bc[1] = rsqrtf(6.28318530717958648f * sv0);
        bc[2] = -0.5f / sv0;
        bc[3] = rsqrtf(6.28318530717958648f * sv1);
        bc[4] = -0.5f / sv1;
    }
    __syncthreads();
    float mu = bc[0], c0 = bc[1], h0 = bc[2], c1 = bc[3], h1 = bc[4];
    #pragma unroll
    for (int i = 0; i < 4; i++) {
        int idx = t + i * 256;
        float bmu = (float)(idx >> 1) * (1.0f / 511.0f);
        float d = bmu - mu;
        float c = (idx & 1) ? c1 : c0;
        float h = (idx & 1) ? h1 : h0;
        s[idx] = c * __expf(h * d * d);
    }
}

// ------------------------- launch ------------------------------------------
extern "C" void kernel_launch(void* const* d_in, const int* in_sizes, int n_in,
                              void* d_out, int out_size)
{
    (void)in_sizes; (void)n_in; (void)out_size;
    const float* dk   = (const float*)d_in[0];   // (1,512,2048)
    const float* dq   = (const float*)d_in[1];   // (1,16,2048,128)
    const float* dWk  = (const float*)d_in[2];   // (2048,2048)
    const float* dWv  = (const float*)d_in[3];   // (2048,2048)
    const float* dWo  = (const float*)d_in[4];   // (2048,2048)
    const float* dwmu = (const float*)d_in[5];   // (1024,)
    const float* dwsg = (const float*)d_in[6];   // (1024,)
    float* dout = (float*)d_out;                 // (1,2048,2048)

    compute_G2_host();

    float *pG2, *pKVt, *pKV2, *pS, *pCtx;
    cudaGetSymbolAddress((void**)&pG2,  g_G2);
    cudaGetSymbolAddress((void**)&pKVt, g_KVt);
    cudaGetSymbolAddress((void**)&pKV2, g_KV2);
    cudaGetSymbolAddress((void**)&pS,   g_S);
    cudaGetSymbolAddress((void**)&pCtx, g_ctx);

    // 0: bring G2 on-device (ATS read of static host array)
    {
        int n4 = (1024 * 512) / 4;
        copy_g2_kernel<<<(n4 + 255) / 256, 256>>>(
            reinterpret_cast<const float4*>(hG2),
            reinterpret_cast<float4*>(pG2), n4);
    }

    // 1: KVt[z*2048 + j][l] = sum_d W[j,d] * k[l,d]
    {
        long long sA = (long long)(dWv - dWk);
        dim3 g(512 / 128, 2048 / 128, 2);
        gemm128<true><<<g, 256>>>(dWk, 2048, sA,
                                  dk,  2048, 0,
                                  pKVt, 512, 2048LL * 512,
                                  2048, 1.0f);
    }
    // 2: KV2[n][j] = sum_l G2[n][l] * KVt[j][l]
    {
        dim3 g(4096 / 128, 1024 / 128, 1);
        gemm128<true><<<g, 256>>>(pG2, 512, 0,
                                  pKVt, 512, 0,
                                  pKV2, 4096, 0,
                                  512, 1.0f);
    }
    // 3: scores[h][q][n] = (1/sqrt(128)) * sum_d q[h,q,d] * keys[n, h*128+d]
    {
        dim3 g(1024 / 128, 2048 / 128, 16);
        gemm128<true><<<g, 256>>>(dq, 128, 2048LL * 128,
                                  pKV2, 4096, 128,
                                  pS, 1024, 2048LL * 1024,
                                  128, 0.08838834764831845f);
    }
    // 4: mu/sigma reduction + r (in place)
    row_r_kernel<<<16 * 2048, 256>>>(pS, dwmu, dwsg);

    // 5: ctx[q][h*128+d] = sum_n r[h,q,n] * values[n, h*128+d]
    {
        dim3 g(1, 2048 / 128, 16);
        gemm128<false><<<g, 256>>>(pS, 1024, 2048LL * 1024,
                                   pKV2 + 2048, 4096, 128,
                                   pCtx, 2048, 128,
                                   1024, 1.0f);
    }
    // 6: out[q][o] = sum_c ctx[q][c] * W_out[o][c]
    {
        dim3 g(2048 / 128, 2048 / 128, 1);
        gemm128<true><<<g, 256>>>(pCtx, 2048, 0,
                                  dWo, 2048, 0,
                                  dout, 2048, 0,
                                  2048, 1.0f);
    }
}

// round 4
// speedup vs baseline: 1.9260x; 1.4920x over previous
#include <cuda_runtime.h>
#include <cuda_bf16.h>
#include <math.h>
#include <string.h>
#include <stdint.h>

// ---------------------------------------------------------------------------
//  H=16, D=128, d=2048, N_BASIS=1024, l=512, QLEN=2048, RIDGE=0.5
//  All GEMMs in K-major A·B^T form on HMMA (mma.sync m16n8k16 bf16) with
//  split-bf16 (x = hi + lo) 3-pass emulation for ~fp32 accuracy.
// ---------------------------------------------------------------------------

typedef __nv_bfloat16 bf16;

// ------------------------- device scratch (static) -------------------------
__device__ bf16 g_Wh [2u*2048*2048], g_Wl [2u*2048*2048];   // W_key|W_val split
__device__ bf16 g_kh [512*2048],     g_kl [512*2048];
__device__ bf16 g_qh [16*2048*128],  g_ql [16*2048*128];
__device__ bf16 g_Woh[2048*2048],    g_Wol[2048*2048];
__device__ bf16 g_G2h[1024*512],     g_G2l[1024*512];
__device__ bf16 g_KVth[4096*512],    g_KVtl[4096*512];
__device__ bf16 g_keysh[1024*2048],  g_keysl[1024*2048];    // keys[n][j]
__device__ bf16 g_valTh[2048*1024],  g_valTl[2048*1024];    // values^T[j][n]
__device__ float g_S[16u*2048*1024];                        // scores (fp32)
__device__ bf16 g_rh[16u*2048*1024], g_rl[16u*2048*1024];   // r split
__device__ bf16 g_ctxh[2048*2048],   g_ctxl[2048*2048];

// ------------------------- host-side G2 (fp64 solve) -----------------------
static double hF[1024 * 1024];
static double hA[1024 * 1024];
static double hX[1024 * 1024];
static __align__(16) bf16 hG2h[1024 * 512];
static __align__(16) bf16 hG2l[1024 * 512];
static double hbmu[1024], hbsig[1024];
static int    hlo[1024], hhi[1024];

static void compute_G2_host()
{
    const int n = 1024, P = 1024;
    for (int i = 0; i < 512; i++) {
        double m = (double)i / 511.0;
        hbmu[2*i] = m;  hbmu[2*i+1] = m;
        hbsig[2*i] = 0.005; hbsig[2*i+1] = 0.01;
    }
    const double shift = 1.0 / 1024.0;
    const double start = -0.5 + shift, stop = 1.5 - shift;
    const double step  = (stop - start) / (double)(P - 1);
    const double inv_sqrt2pi = 0.39894228040143267794;

    for (int b = 0; b < n; b++) {
        double mu = hbmu[b], sg = hbsig[b];
        double c = inv_sqrt2pi / sg;
        int lo = P, hi = 0;
        for (int p = 0; p < P; p++) {
            double x = start + p * step;
            double t = (x - mu) / sg;
            double v = (fabs(t) < 38.0) ? c * exp(-0.5 * t * t) : 0.0;
            hF[(long)b * P + p] = v;
            if (v != 0.0) { if (p < lo) lo = p; if (p + 1 > hi) hi = p + 1; }
        }
        hlo[b] = lo; hhi[b] = hi;
    }

    memset(hA, 0, sizeof(hA));
    for (int i = 0; i < n; i++) {
        for (int j = i; j < n; j++) {
            int lo = hlo[i] > hlo[j] ? hlo[i] : hlo[j];
            int hi = hhi[i] < hhi[j] ? hhi[i] : hhi[j];
            double s = 0.0;
            if (lo < hi) {
                const double* fi = &hF[(long)i * P];
                const double* fj = &hF[(long)j * P];
                for (int p = lo; p < hi; p++) s += fi[p] * fj[p];
            }
            if (i == j) s += 0.5;
            hA[(long)i * n + j] = s;
            hA[(long)j * n + i] = s;
        }
    }
    // Cholesky (lower), in place
    for (int i = 0; i < n; i++) {
        for (int j = 0; j <= i; j++) {
            double s = hA[(long)i * n + j];
            const double* Li = &hA[(long)i * n];
            const double* Lj = &hA[(long)j * n];
            for (int k2 = 0; k2 < j; k2++) s -= Li[k2] * Lj[k2];
            if (j == i) hA[(long)i * n + i] = sqrt(s);
            else        hA[(long)i * n + j] = s / hA[(long)j * n + j];
        }
    }
    memcpy(hX, hF, sizeof(hX));
    for (int i = 0; i < n; i++) {
        double* xi = &hX[(long)i * P];
        const double* Li = &hA[(long)i * n];
        for (int k2 = 0; k2 < i; k2++) {
            double l = Li[k2];
            if (l != 0.0) {
                const double* xk = &hX[(long)k2 * P];
                for (int p = 0; p < P; p++) xi[p] -= l * xk[p];
            }
        }
        double inv = 1.0 / hA[(long)i * n + i];
        for (int p = 0; p < P; p++) xi[p] *= inv;
    }
    for (int i = n - 1; i >= 0; i--) {
        double* xi = &hX[(long)i * P];
        for (int k2 = i + 1; k2 < n; k2++) {
            double l = hA[(long)k2 * n + i];
            if (l != 0.0) {
                const double* xk = &hX[(long)k2 * P];
                for (int p = 0; p < P; p++) xi[p] -= l * xk[p];
            }
        }
        double inv = 1.0 / hA[(long)i * n + i];
        for (int p = 0; p < P; p++) xi[p] *= inv;
    }
    for (int b = 0; b < n; b++)
        for (int l = 0; l < 512; l++) {
            float v = (float)hX[(long)b * P + 256 + l];
            bf16 h = __float2bfloat16(v);
            hG2h[b * 512 + l] = h;
            hG2l[b * 512 + l] = __float2bfloat16(v - __bfloat162float(h));
        }
}

// ------------------------- PTX helpers -------------------------------------
__device__ __forceinline__ uint32_t smem_u32(const void* p) {
    uint32_t a;
    asm("{ .reg .u64 t; cvta.to.shared.u64 t, %1; cvt.u32.u64 %0, t; }" : "=r"(a) : "l"(p));
    return a;
}
__device__ __forceinline__ void ldsm4(uint32_t* r, uint32_t addr) {
    asm volatile("ldmatrix.sync.aligned.m8n8.x4.shared.b16 {%0,%1,%2,%3}, [%4];"
                 : "=r"(r[0]), "=r"(r[1]), "=r"(r[2]), "=r"(r[3]) : "r"(addr));
}
__device__ __forceinline__ void mma16816(float* d,
                                         uint32_t a0, uint32_t a1, uint32_t a2, uint32_t a3,
                                         uint32_t b0, uint32_t b1) {
    asm volatile("mma.sync.aligned.m16n8k16.row.col.f32.bf16.bf16.f32 "
                 "{%0,%1,%2,%3}, {%4,%5,%6,%7}, {%8,%9}, {%0,%1,%2,%3};"
                 : "+f"(d[0]), "+f"(d[1]), "+f"(d[2]), "+f"(d[3])
                 : "r"(a0), "r"(a1), "r"(a2), "r"(a3), "r"(b0), "r"(b1));
}
#define CP_ASYNC16(dst, src) \
    asm volatile("cp.async.cg.shared.global [%0], [%1], 16;" :: "r"(dst), "l"(src) : "memory")
#define CP_COMMIT() asm volatile("cp.async.commit_group;" ::: "memory")
#define CP_WAIT_1()  asm volatile("cp.async.wait_group 1;" ::: "memory")
#define CP_WAIT_0()  asm volatile("cp.async.wait_group 0;" ::: "memory")

// ------------------------- small kernels -----------------------------------
__global__ void split_kernel(const float4* __restrict__ src,
                             uint2* __restrict__ dhi, uint2* __restrict__ dlo, int n4)
{
    int i = blockIdx.x * blockDim.x + threadIdx.x;
    if (i >= n4) return;
    float4 v = src[i];
    bf16 h0 = __float2bfloat16(v.x), h1 = __float2bfloat16(v.y);
    bf16 h2 = __float2bfloat16(v.z), h3 = __float2bfloat16(v.w);
    __nv_bfloat162 ha = {h0, h1}, hb = {h2, h3};
    __nv_bfloat162 la = {__float2bfloat16(v.x - __bfloat162float(h0)),
                         __float2bfloat16(v.y - __bfloat162float(h1))};
    __nv_bfloat162 lb = {__float2bfloat16(v.z - __bfloat162float(h2)),
                         __float2bfloat16(v.w - __bfloat162float(h3))};
    uint2 hh, ll;
    hh.x = *(uint32_t*)&ha; hh.y = *(uint32_t*)&hb;
    ll.x = *(uint32_t*)&la; ll.y = *(uint32_t*)&lb;
    dhi[i] = hh; dlo[i] = ll;
}

__global__ void copy_g2_kernel(const uint4* __restrict__ sh, const uint4* __restrict__ sl,
                               uint4* __restrict__ dh, uint4* __restrict__ dl, int n16)
{
    int i = blockIdx.x * blockDim.x + threadIdx.x;
    if (i < n16) { dh[i] = sh[i]; dl[i] = sl[i]; }
}

// ------------------------- HMMA split GEMM ---------------------------------
// C[m][n] = alpha * sum_k A[m][k]*B[n][k], A,B given as (hi, lo) bf16.
// OUT_MODE 0: fp32 C;  1: split bf16 (Ch, Cl).
// CTA tile 128x128, BK=32, 8 warps (warp tile 64x32), cp.async double buffer.
// Smem rows padded to 40 bf16 (80 B = 5x16B chunks -> conflict-free ldmatrix).
static const int ROWB   = 80;                 // bytes per smem row
static const int TILE_B = 128 * ROWB;         // 10240 B per (hi|lo) tile
static const int OFF_AH = 0, OFF_AL = TILE_B, OFF_BH = 2*TILE_B, OFF_BL = 3*TILE_B;
static const int STAGE_B = 4 * TILE_B;        // 40960
static const int SMEM_BYTES = 2 * STAGE_B;    // 81920

template<int OUT_MODE>
__global__ __launch_bounds__(256, 1)
void mma_gemm(const bf16* __restrict__ Ah, const bf16* __restrict__ Al, int lda, long long sA,
              const bf16* __restrict__ Bh, const bf16* __restrict__ Bl, int ldb, long long sB,
              float* __restrict__ C, bf16* __restrict__ Ch, bf16* __restrict__ Cl,
              int ldc, long long sC, int K, float alpha)
{
    extern __shared__ char dsm[];
    const uint32_t sb = smem_u32(dsm);
    const int tid = threadIdx.x, lane = tid & 31, wid = tid >> 5;
    const int warp_m = wid >> 2, warp_n = wid & 3;      // 2 x 4 warp grid
    const int bx = blockIdx.x, by = blockIdx.y, bz = blockIdx.z;

    const bf16* A0h = Ah + (long long)bz * sA + (long long)(by * 128) * lda;
    const bf16* A0l = Al + (long long)bz * sA + (long long)(by * 128) * lda;
    const bf16* B0h = Bh + (long long)bz * sB + (long long)(bx * 128) * ldb;
    const bf16* B0l = Bl + (long long)bz * sB + (long long)(bx * 128) * ldb;

    // cp.async chunk coords: 512 16B-chunks per 128x32 tile, 2 per thread
    const int c0 = tid, c1 = tid + 256;
    const int r0 = c0 >> 2, q0 = c0 & 3;      // row, col16 (8 bf16 per chunk)
    const int r1 = c1 >> 2, q1 = c1 & 3;

    auto load_stage = [&](int s, int k0) {
        uint32_t d = sb + s * STAGE_B;
        uint32_t d0 = (uint32_t)(r0 * ROWB + q0 * 16);
        uint32_t d1 = (uint32_t)(r1 * ROWB + q1 * 16);
        long long gA0 = (long long)r0 * lda + k0 + q0 * 8;
        long long gA1 = (long long)r1 * lda + k0 + q1 * 8;
        long long gB0 = (long long)r0 * ldb + k0 + q0 * 8;
        long long gB1 = (long long)r1 * ldb + k0 + q1 * 8;
        CP_ASYNC16(d + OFF_AH + d0, A0h + gA0);
        CP_ASYNC16(d + OFF_AH + d1, A0h + gA1);
        CP_ASYNC16(d + OFF_AL + d0, A0l + gA0);
        CP_ASYNC16(d + OFF_AL + d1, A0l + gA1);
        CP_ASYNC16(d + OFF_BH + d0, B0h + gB0);
        CP_ASYNC16(d + OFF_BH + d1, B0h + gB1);
        CP_ASYNC16(d + OFF_BL + d0, B0l + gB0);
        CP_ASYNC16(d + OFF_BL + d1, B0l + gB1);
    };

    // ldmatrix per-lane base offsets
    const int lr = lane & 15;
    const uint32_t lc = (uint32_t)((lane >> 4) * 16);
    uint32_t aoff[4], boff[2];
    #pragma unroll
    for (int mt = 0; mt < 4; mt++)
        aoff[mt] = (uint32_t)((warp_m * 64 + mt * 16 + lr) * ROWB) + lc;
    #pragma unroll
    for (int n2 = 0; n2 < 2; n2++)
        boff[n2] = (uint32_t)((warp_n * 32 + n2 * 16 + lr) * ROWB) + lc;

    float acc[4][4][4];
    #pragma unroll
    for (int i = 0; i < 4; i++)
        #pragma unroll
        for (int j = 0; j < 4; j++)
            #pragma unroll
            for (int v = 0; v < 4; v++) acc[i][j][v] = 0.f;

    const int nk = K >> 5;
    load_stage(0, 0);
    CP_COMMIT();

    for (int t = 0; t < nk; t++) {
        if (t + 1 < nk) { load_stage((t + 1) & 1, (t + 1) << 5); CP_COMMIT(); CP_WAIT_1(); }
        else            { CP_WAIT_0(); }
        __syncthreads();

        const uint32_t s = sb + (t & 1) * STAGE_B;
        #pragma unroll
        for (int k16 = 0; k16 < 2; k16++) {
            const uint32_t kb = (uint32_t)(k16 * 32);
            uint32_t ah[4][4], al[4][4], bh[2][4], bl[2][4];
            #pragma unroll
            for (int mt = 0; mt < 4; mt++) ldsm4(ah[mt], s + OFF_AH + aoff[mt] + kb);
            #pragma unroll
            for (int n2 = 0; n2 < 2; n2++) ldsm4(bh[n2], s + OFF_BH + boff[n2] + kb);
            #pragma unroll
            for (int mt = 0; mt < 4; mt++)
                #pragma unroll
                for (int nt = 0; nt < 4; nt++) {
                    const uint32_t* b = bh[nt >> 1];
                    mma16816(acc[mt][nt], ah[mt][0], ah[mt][1], ah[mt][2], ah[mt][3],
                             (nt & 1) ? b[1] : b[0], (nt & 1) ? b[3] : b[2]);
                }
            #pragma unroll
            for (int n2 = 0; n2 < 2; n2++) ldsm4(bl[n2], s + OFF_BL + boff[n2] + kb);
            #pragma unroll
            for (int mt = 0; mt < 4; mt++)
                #pragma unroll
                for (int nt = 0; nt < 4; nt++) {
                    const uint32_t* b = bl[nt >> 1];
                    mma16816(acc[mt][nt], ah[mt][0], ah[mt][1], ah[mt][2], ah[mt][3],
                             (nt & 1) ? b[1] : b[0], (nt & 1) ? b[3] : b[2]);
                }
            #pragma unroll
            for (int mt = 0; mt < 4; mt++) ldsm4(al[mt], s + OFF_AL + aoff[mt] + kb);
            #pragma unroll
            for (int mt = 0; mt < 4; mt++)
                #pragma unroll
                for (int nt = 0; nt < 4; nt++) {
                    const uint32_t* b = bh[nt >> 1];
                    mma16816(acc[mt][nt], al[mt][0], al[mt][1], al[mt][2], al[mt][3],
                             (nt & 1) ? b[1] : b[0], (nt & 1) ? b[3] : b[2]);
                }
        }
        __syncthreads();
    }

    // epilogue
    const int group = lane >> 2, tig = lane & 3;
    #pragma unroll
    for (int mt = 0; mt < 4; mt++) {
        #pragma unroll
        for (int nt = 0; nt < 4; nt++) {
            int row = by * 128 + warp_m * 64 + mt * 16 + group;
            int col = bx * 128 + warp_n * 32 + nt * 8 + tig * 2;
            float v0 = alpha * acc[mt][nt][0], v1 = alpha * acc[mt][nt][1];
            float v2 = alpha * acc[mt][nt][2], v3 = alpha * acc[mt][nt][3];
            if (OUT_MODE == 0) {
                float* p0 = C + (long long)bz * sC + (long long)row * ldc + col;
                float* p1 = p0 + 8LL * ldc;
                *(float2*)p0 = make_float2(v0, v1);
                *(float2*)p1 = make_float2(v2, v3);
            } else {
                long long o0 = (long long)bz * sC + (long long)row * ldc + col;
                long long o1 = o0 + 8LL * ldc;
                bf16 h0 = __float2bfloat16(v0), h1 = __float2bfloat16(v1);
                bf16 h2 = __float2bfloat16(v2), h3 = __float2bfloat16(v3);
                __nv_bfloat162 hh0 = {h0, h1}, hh1 = {h2, h3};
                __nv_bfloat162 ll0 = {__float2bfloat16(v0 - __bfloat162float(h0)),
                                      __float2bfloat16(v1 - __bfloat162float(h1))};
                __nv_bfloat162 ll1 = {__float2bfloat16(v2 - __bfloat162float(h2)),
                                      __float2bfloat16(v3 - __bfloat162float(h3))};
                *(__nv_bfloat162*)(Ch + o0) = hh0;
                *(__nv_bfloat162*)(Cl + o0) = ll0;
                *(__nv_bfloat162*)(Ch + o1) = hh1;
                *(__nv_bfloat162*)(Cl + o1) = ll1;
            }
        }
    }
}

// ------------------------- row_r: mu/sigma -> split r ----------------------
__global__ __launch_bounds__(256)
void row_r_kernel(const float* __restrict__ S,
                  bf16* __restrict__ Rh, bf16* __restrict__ Rl,
                  const float* __restrict__ wmu,
                  const float* __restrict__ wsg)
{
    long long row = blockIdx.x;
    const float* s = S + row * 1024;
    int t = threadIdx.x;

    float pm = 0.f, ps = 0.f;
    #pragma unroll
    for (int i = 0; i < 4; i++) {
        int idx = t + i * 256;
        float v = s[idx];
        pm += v * wmu[idx];
        ps += v * wsg[idx];
    }
    #pragma unroll
    for (int o = 16; o > 0; o >>= 1) {
        pm += __shfl_down_sync(0xffffffffu, pm, o);
        ps += __shfl_down_sync(0xffffffffu, ps, o);
    }
    __shared__ float rm[8], rs[8];
    __shared__ float bc[5];
    int w = t >> 5, lane = t & 31;
    if (lane == 0) { rm[w] = pm; rs[w] = ps; }
    __syncthreads();
    if (t == 0) {
        float m = 0.f, g = 0.f;
        #pragma unroll
        for (int i = 0; i < 8; i++) { m += rm[i]; g += rs[i]; }
        float mu  = 1.f / (1.f + __expf(-m));
        float sp  = (g > 20.f) ? g : log1pf(__expf(g));
        float var = fmaxf(sp, 1e-4f);
        float sv0 = var + 2.5e-5f;
        float sv1 = var + 1.0e-4f;
        bc[0] = mu;
        bc[1] = rsqrtf(6.28318530717958648f * sv0);
        bc[2] = -0.5f / sv0;
        bc[3] = rsqrtf(6.28318530717958648f * sv1);
        bc[4] = -0.5f / sv1;
    }
    __syncthreads();
    float mu = bc[0], c0 = bc[1], h0 = bc[2], c1 = bc[3], h1 = bc[4];
    #pragma unroll
    for (int i = 0; i < 4; i++) {
        int idx = t + i * 256;
        float bmu = (float)(idx >> 1) * (1.0f / 511.0f);
        float dd = bmu - mu;
        float c = (idx & 1) ? c1 : c0;
        float h = (idx & 1) ? h1 : h0;
        float v = c * __expf(h * dd * dd);
        bf16 vh = __float2bfloat16(v);
        Rh[row * 1024 + idx] = vh;
        Rl[row * 1024 + idx] = __float2bfloat16(v - __bfloat162float(vh));
    }
}

// ------------------------- launch ------------------------------------------
extern "C" void kernel_launch(void* const* d_in, const int* in_sizes, int n_in,
                              void* d_out, int out_size)
{
    (void)in_sizes; (void)n_in; (void)out_size;
    const float* dk   = (const float*)d_in[0];
    const float* dq   = (const float*)d_in[1];
    const float* dWk  = (const float*)d_in[2];
    const float* dWv  = (const float*)d_in[3];
    const float* dWo  = (const float*)d_in[4];
    const float* dwmu = (const float*)d_in[5];
    const float* dwsg = (const float*)d_in[6];
    float* dout = (float*)d_out;

    compute_G2_host();

    bf16 *pWh, *pWl, *pkh, *pkl, *pqh, *pql, *pWoh, *pWol, *pG2h, *pG2l;
    bf16 *pKVth, *pKVtl, *pkeysh, *pkeysl, *pvalTh, *pvalTl;
    bf16 *prh, *prl, *pctxh, *pctxl;
    float *pS;
    cudaGetSymbolAddress((void**)&pWh,   g_Wh);   cudaGetSymbolAddress((void**)&pWl,   g_Wl);
    cudaGetSymbolAddress((void**)&pkh,   g_kh);   cudaGetSymbolAddress((void**)&pkl,   g_kl);
    cudaGetSymbolAddress((void**)&pqh,   g_qh);   cudaGetSymbolAddress((void**)&pql,   g_ql);
    cudaGetSymbolAddress((void**)&pWoh,  g_Woh);  cudaGetSymbolAddress((void**)&pWol,  g_Wol);
    cudaGetSymbolAddress((void**)&pG2h,  g_G2h);  cudaGetSymbolAddress((void**)&pG2l,  g_G2l);
    cudaGetSymbolAddress((void**)&pKVth, g_KVth); cudaGetSymbolAddress((void**)&pKVtl, g_KVtl);
    cudaGetSymbolAddress((void**)&pkeysh,g_keysh);cudaGetSymbolAddress((void**)&pkeysl,g_keysl);
    cudaGetSymbolAddress((void**)&pvalTh,g_valTh);cudaGetSymbolAddress((void**)&pvalTl,g_valTl);
    cudaGetSymbolAddress((void**)&prh,   g_rh);   cudaGetSymbolAddress((void**)&prl,   g_rl);
    cudaGetSymbolAddress((void**)&pctxh, g_ctxh); cudaGetSymbolAddress((void**)&pctxl, g_ctxl);
    cudaGetSymbolAddress((void**)&pS,    g_S);

    cudaFuncSetAttribute(mma_gemm<0>, cudaFuncAttributeMaxDynamicSharedMemorySize, SMEM_BYTES);
    cudaFuncSetAttribute(mma_gemm<1>, cudaFuncAttributeMaxDynamicSharedMemorySize, SMEM_BYTES);

    // splits of raw inputs
    {
        int n4;
        n4 = 2048 * 2048 / 4;
        split_kernel<<<(n4 + 255) / 256, 256>>>((const float4*)dWk, (uint2*)pWh, (uint2*)pWl, n4);
        split_kernel<<<(n4 + 255) / 256, 256>>>((const float4*)dWv,
                                                (uint2*)(pWh + 2048 * 2048), (uint2*)(pWl + 2048 * 2048), n4);
        split_kernel<<<(n4 + 255) / 256, 256>>>((const float4*)dWo, (uint2*)pWoh, (uint2*)pWol, n4);
        n4 = 512 * 2048 / 4;
        split_kernel<<<(n4 + 255) / 256, 256>>>((const float4*)dk, (uint2*)pkh, (uint2*)pkl, n4);
        n4 = 16 * 2048 * 128 / 4;
        split_kernel<<<(n4 + 255) / 256, 256>>>((const float4*)dq, (uint2*)pqh, (uint2*)pql, n4);
        int n16 = 1024 * 512 * 2 / 16;
        copy_g2_kernel<<<(n16 + 255) / 256, 256>>>((const uint4*)hG2h, (const uint4*)hG2l,
                                                   (uint4*)pG2h, (uint4*)pG2l, n16);
    }

    // 1: KVt[z*2048+j][l] = W[z][j]·k[l]     M=2048 N=512 K=2048, batch 2
    {
        dim3 g(4, 16, 2);
        mma_gemm<1><<<g, 256, SMEM_BYTES>>>(pWh, pWl, 2048, 2048LL * 2048,
                                            pkh, pkl, 2048, 0,
                                            nullptr, pKVth, pKVtl, 512, 2048LL * 512,
                                            2048, 1.0f);
    }
    // 2a: keys[n][j] = G2[n]·KVt_key[j]      M=1024 N=2048 K=512
    {
        dim3 g(16, 8, 1);
        mma_gemm<1><<<g, 256, SMEM_BYTES>>>(pG2h, pG2l, 512, 0,
                                            pKVth, pKVtl, 512, 0,
                                            nullptr, pkeysh, pkeysl, 2048, 0,
                                            512, 1.0f);
    }
    // 2b: valT[j][n] = KVt_val[j]·G2[n]      M=2048 N=1024 K=512
    {
        dim3 g(8, 16, 1);
        mma_gemm<1><<<g, 256, SMEM_BYTES>>>(pKVth + 2048LL * 512, pKVtl + 2048LL * 512, 512, 0,
                                            pG2h, pG2l, 512, 0,
                                            nullptr, pvalTh, pvalTl, 1024, 0,
                                            512, 1.0f);
    }
    // 3: S[h][q][n] = alpha * q[h,q]·keys[n, h*128:]   M=2048 N=1024 K=128, batch 16
    {
        dim3 g(8, 16, 16);
        mma_gemm<0><<<g, 256, SMEM_BYTES>>>(pqh, pql, 128, 2048LL * 128,
                                            pkeysh, pkeysl, 2048, 128,
                                            pS, nullptr, nullptr, 1024, 2048LL * 1024,
                                            128, 0.08838834764831845f);
    }
    // 4: mu/sigma + r (split out)
    row_r_kernel<<<16 * 2048, 256>>>(pS, prh, prl, dwmu, dwsg);

    // 5: ctx[q][h*128+j] = r[h][q]·valT[h*128+j]   M=2048 N=128 K=1024, batch 16
    {
        dim3 g(1, 16, 16);
        mma_gemm<1><<<g, 256, SMEM_BYTES>>>(prh, prl, 1024, 2048LL * 1024,
                                            pvalTh, pvalTl, 1024, 128LL * 1024,
                                            nullptr, pctxh, pctxl, 2048, 128,
                                            1024, 1.0f);
    }
    // 6: out[q][o] = ctx[q]·Wo[o]            M=2048 N=2048 K=2048
    {
        dim3 g(16, 16, 1);
        mma_gemm<0><<<g, 256, SMEM_BYTES>>>(pctxh, pctxl, 2048, 0,
                                            pWoh, pWol, 2048, 0,
                                            dout, nullptr, nullptr, 2048, 0,
                                            2048, 1.0f);
    }
}

// round 5
// speedup vs baseline: 2.0079x; 1.0425x over previous
#include <cuda_runtime.h>
#include <cuda_bf16.h>
#include <math.h>
#include <string.h>
#include <stdint.h>

// ---------------------------------------------------------------------------
//  H=16, D=128, d=2048, N_BASIS=1024, l=512, QLEN=2048, RIDGE=0.5
//  GEMMs on HMMA (mma.sync m16n8k16 bf16), split-bf16 3-pass for ~fp32.
//  r[q][n] is analytic: scores are never materialized; GEMM5's A operand is
//  synthesized in registers from 5 per-row scalars.
// ---------------------------------------------------------------------------

typedef __nv_bfloat16 bf16;

// ------------------------- device scratch (static) -------------------------
__device__ bf16 g_Wh [2u*2048*2048], g_Wl [2u*2048*2048];   // W_key|W_val split
__device__ bf16 g_kh [512*2048],     g_kl [512*2048];
__device__ bf16 g_qh [16*2048*128],  g_ql [16*2048*128];
__device__ bf16 g_Woh[2048*2048],    g_Wol[2048*2048];
__device__ bf16 g_G2h[1024*512],     g_G2l[1024*512];
__device__ bf16 g_KVth[4096*512],    g_KVtl[4096*512];
__device__ bf16 g_keysh[1024*2048],  g_keysl[1024*2048];    // keys[n][j]
__device__ bf16 g_valTh[2048*1024],  g_valTl[2048*1024];    // values^T[j][n]
__device__ float g_part[16u*16*128*16];                     // 2 MB mu/sg partials
__device__ float g_params[32768u*8];                        // 1 MB row params
__device__ bf16 g_ctxh[2048*2048],   g_ctxl[2048*2048];

// ------------------------- host-side G2 (fp64 solve) -----------------------
static double hF[1024 * 1024];
static double hA[1024 * 1024];
static double hX[1024 * 1024];
static __align__(16) bf16 hG2h[1024 * 512];
static __align__(16) bf16 hG2l[1024 * 512];
static double hbmu[1024], hbsig[1024];
static int    hlo[1024], hhi[1024];

static void compute_G2_host()
{
    const int n = 1024, P = 1024;
    for (int i = 0; i < 512; i++) {
        double m = (double)i / 511.0;
        hbmu[2*i] = m;  hbmu[2*i+1] = m;
        hbsig[2*i] = 0.005; hbsig[2*i+1] = 0.01;
    }
    const double shift = 1.0 / 1024.0;
    const double start = -0.5 + shift, stop = 1.5 - shift;
    const double step  = (stop - start) / (double)(P - 1);
    const double inv_sqrt2pi = 0.39894228040143267794;

    for (int b = 0; b < n; b++) {
        double mu = hbmu[b], sg = hbsig[b];
        double c = inv_sqrt2pi / sg;
        int lo = P, hi = 0;
        for (int p = 0; p < P; p++) {
            double x = start + p * step;
            double t = (x - mu) / sg;
            double v = (fabs(t) < 38.0) ? c * exp(-0.5 * t * t) : 0.0;
            hF[(long)b * P + p] = v;
            if (v != 0.0) { if (p < lo) lo = p; if (p + 1 > hi) hi = p + 1; }
        }
        hlo[b] = lo; hhi[b] = hi;
    }

    memset(hA, 0, sizeof(hA));
    for (int i = 0; i < n; i++) {
        for (int j = i; j < n; j++) {
            int lo = hlo[i] > hlo[j] ? hlo[i] : hlo[j];
            int hi = hhi[i] < hhi[j] ? hhi[i] : hhi[j];
            double s = 0.0;
            if (lo < hi) {
                const double* fi = &hF[(long)i * P];
                const double* fj = &hF[(long)j * P];
                for (int p = lo; p < hi; p++) s += fi[p] * fj[p];
            }
            if (i == j) s += 0.5;
            hA[(long)i * n + j] = s;
            hA[(long)j * n + i] = s;
        }
    }
    // Cholesky (lower), in place
    for (int i = 0; i < n; i++) {
        for (int j = 0; j <= i; j++) {
            double s = hA[(long)i * n + j];
            const double* Li = &hA[(long)i * n];
            const double* Lj = &hA[(long)j * n];
            for (int k2 = 0; k2 < j; k2++) s -= Li[k2] * Lj[k2];
            if (j == i) hA[(long)i * n + i] = sqrt(s);
            else        hA[(long)i * n + j] = s / hA[(long)j * n + j];
        }
    }
    memcpy(hX, hF, sizeof(hX));
    for (int i = 0; i < n; i++) {
        double* xi = &hX[(long)i * P];
        const double* Li = &hA[(long)i * n];
        for (int k2 = 0; k2 < i; k2++) {
            double l = Li[k2];
            if (l != 0.0) {
                const double* xk = &hX[(long)k2 * P];
                for (int p = 0; p < P; p++) xi[p] -= l * xk[p];
            }
        }
        double inv = 1.0 / hA[(long)i * n + i];
        for (int p = 0; p < P; p++) xi[p] *= inv;
    }
    for (int i = n - 1; i >= 0; i--) {
        double* xi = &hX[(long)i * P];
        for (int k2 = i + 1; k2 < n; k2++) {
            double l = hA[(long)k2 * n + i];
            if (l != 0.0) {
                const double* xk = &hX[(long)k2 * P];
                for (int p = 0; p < P; p++) xi[p] -= l * xk[p];
            }
        }
        double inv = 1.0 / hA[(long)i * n + i];
        for (int p = 0; p < P; p++) xi[p] *= inv;
    }
    for (int b = 0; b < n; b++)
        for (int l = 0; l < 512; l++) {
            float v = (float)hX[(long)b * P + 256 + l];
            bf16 h = __float2bfloat16(v);
            hG2h[b * 512 + l] = h;
            hG2l[b * 512 + l] = __float2bfloat16(v - __bfloat162float(h));
        }
}

// ------------------------- PTX helpers -------------------------------------
__device__ __forceinline__ uint32_t smem_u32(const void* p) {
    uint32_t a;
    asm("{ .reg .u64 t; cvta.to.shared.u64 t, %1; cvt.u32.u64 %0, t; }" : "=r"(a) : "l"(p));
    return a;
}
__device__ __forceinline__ void ldsm4(uint32_t* r, uint32_t addr) {
    asm volatile("ldmatrix.sync.aligned.m8n8.x4.shared.b16 {%0,%1,%2,%3}, [%4];"
                 : "=r"(r[0]), "=r"(r[1]), "=r"(r[2]), "=r"(r[3]) : "r"(addr));
}
__device__ __forceinline__ void mma16816(float* d,
                                         uint32_t a0, uint32_t a1, uint32_t a2, uint32_t a3,
                                         uint32_t b0, uint32_t b1) {
    asm volatile("mma.sync.aligned.m16n8k16.row.col.f32.bf16.bf16.f32 "
                 "{%0,%1,%2,%3}, {%4,%5,%6,%7}, {%8,%9}, {%0,%1,%2,%3};"
                 : "+f"(d[0]), "+f"(d[1]), "+f"(d[2]), "+f"(d[3])
                 : "r"(a0), "r"(a1), "r"(a2), "r"(a3), "r"(b0), "r"(b1));
}
#define CP_ASYNC16(dst, src) \
    asm volatile("cp.async.cg.shared.global [%0], [%1], 16;" :: "r"(dst), "l"(src) : "memory")
#define CP_COMMIT() asm volatile("cp.async.commit_group;" ::: "memory")
#define CP_WAIT_1()  asm volatile("cp.async.wait_group 1;" ::: "memory")
#define CP_WAIT_0()  asm volatile("cp.async.wait_group 0;" ::: "memory")

// ------------------------- small kernels -----------------------------------
__global__ void split_kernel(const float4* __restrict__ src,
                             uint2* __restrict__ dhi, uint2* __restrict__ dlo, int n4)
{
    int i = blockIdx.x * blockDim.x + threadIdx.x;
    if (i >= n4) return;
    float4 v = src[i];
    bf16 h0 = __float2bfloat16(v.x), h1 = __float2bfloat16(v.y);
    bf16 h2 = __float2bfloat16(v.z), h3 = __float2bfloat16(v.w);
    __nv_bfloat162 ha = {h0, h1}, hb = {h2, h3};
    __nv_bfloat162 la = {__float2bfloat16(v.x - __bfloat162float(h0)),
                         __float2bfloat16(v.y - __bfloat162float(h1))};
    __nv_bfloat162 lb = {__float2bfloat16(v.z - __bfloat162float(h2)),
                         __float2bfloat16(v.w - __bfloat162float(h3))};
    uint2 hh, ll;
    hh.x = *(uint32_t*)&ha; hh.y = *(uint32_t*)&hb;
    ll.x = *(uint32_t*)&la; ll.y = *(uint32_t*)&lb;
    dhi[i] = hh; dlo[i] = ll;
}

__global__ void copy_g2_kernel(const uint4* __restrict__ sh, const uint4* __restrict__ sl,
                               uint4* __restrict__ dh, uint4* __restrict__ dl, int n16)
{
    int i = blockIdx.x * blockDim.x + threadIdx.x;
    if (i < n16) { dh[i] = sh[i]; dl[i] = sl[i]; }
}

// fold 8 n-tile partials per row -> (mu, c0, h0, c1, h1)
__global__ void reduce_params(const float* __restrict__ gpart, float* __restrict__ params)
{
    int row = blockIdx.x * 256 + threadIdx.x;   // 32768 rows
    float m = 0.f, g = 0.f;
    #pragma unroll
    for (int b = 0; b < 8; b++) {
        m += gpart[row * 16 + b * 2 + 0];
        g += gpart[row * 16 + b * 2 + 1];
    }
    float mu  = 1.f / (1.f + __expf(-m));
    float sp  = (g > 20.f) ? g : log1pf(__expf(g));
    float var = fmaxf(sp, 1e-4f);
    float sv0 = var + 2.5e-5f;
    float sv1 = var + 1.0e-4f;
    params[row * 8 + 0] = mu;
    params[row * 8 + 1] = rsqrtf(6.28318530717958648f * sv0);
    params[row * 8 + 2] = -0.5f / sv0;
    params[row * 8 + 3] = rsqrtf(6.28318530717958648f * sv1);
    params[row * 8 + 4] = -0.5f / sv1;
}

// ------------------------- HMMA split GEMM ---------------------------------
// C[m][n] = alpha * sum_k A[m][k]*B[n][k], A,B given as (hi, lo) bf16.
// OUT_MODE 0: fp32 C;  1: split bf16 (Ch, Cl);  2: no C — per-row partial
// reductions of (alpha*C)·wmu and ·wsg written to gpart (scores GEMM).
static const int ROWB   = 80;
static const int TILE_B = 128 * ROWB;
static const int OFF_AH = 0, OFF_AL = TILE_B, OFF_BH = 2*TILE_B, OFF_BL = 3*TILE_B;
static const int STAGE_B = 4 * TILE_B;        // 40960
static const int SMEM_BYTES = 2 * STAGE_B;    // 81920

template<int OUT_MODE>
__global__ __launch_bounds__(256, 1)
void mma_gemm(const bf16* __restrict__ Ah, const bf16* __restrict__ Al, int lda, long long sA,
              const bf16* __restrict__ Bh, const bf16* __restrict__ Bl, int ldb, long long sB,
              float* __restrict__ C, bf16* __restrict__ Ch, bf16* __restrict__ Cl,
              int ldc, long long sC, int K, float alpha,
              const float* __restrict__ wmu, const float* __restrict__ wsg,
              float* __restrict__ gpart)
{
    extern __shared__ char dsm[];
    const uint32_t sb = smem_u32(dsm);
    const int tid = threadIdx.x, lane = tid & 31, wid = tid >> 5;
    const int warp_m = wid >> 2, warp_n = wid & 3;
    const int bx = blockIdx.x, by = blockIdx.y, bz = blockIdx.z;

    const bf16* A0h = Ah + (long long)bz * sA + (long long)(by * 128) * lda;
    const bf16* A0l = Al + (long long)bz * sA + (long long)(by * 128) * lda;
    const bf16* B0h = Bh + (long long)bz * sB + (long long)(bx * 128) * ldb;
    const bf16* B0l = Bl + (long long)bz * sB + (long long)(bx * 128) * ldb;

    const int c0 = tid, c1 = tid + 256;
    const int r0 = c0 >> 2, q0 = c0 & 3;
    const int r1 = c1 >> 2, q1 = c1 & 3;

    auto load_stage = [&](int s, int k0) {
        uint32_t d = sb + s * STAGE_B;
        uint32_t d0 = (uint32_t)(r0 * ROWB + q0 * 16);
        uint32_t d1 = (uint32_t)(r1 * ROWB + q1 * 16);
        long long gA0 = (long long)r0 * lda + k0 + q0 * 8;
        long long gA1 = (long long)r1 * lda + k0 + q1 * 8;
        long long gB0 = (long long)r0 * ldb + k0 + q0 * 8;
        long long gB1 = (long long)r1 * ldb + k0 + q1 * 8;
        CP_ASYNC16(d + OFF_AH + d0, A0h + gA0);
        CP_ASYNC16(d + OFF_AH + d1, A0h + gA1);
        CP_ASYNC16(d + OFF_AL + d0, A0l + gA0);
        CP_ASYNC16(d + OFF_AL + d1, A0l + gA1);
        CP_ASYNC16(d + OFF_BH + d0, B0h + gB0);
        CP_ASYNC16(d + OFF_BH + d1, B0h + gB1);
        CP_ASYNC16(d + OFF_BL + d0, B0l + gB0);
        CP_ASYNC16(d + OFF_BL + d1, B0l + gB1);
    };

    const int lr = lane & 15;
    const uint32_t lc = (uint32_t)((lane >> 4) * 16);
    uint32_t aoff[4], boff[2];
    #pragma unroll
    for (int mt = 0; mt < 4; mt++)
        aoff[mt] = (uint32_t)((warp_m * 64 + mt * 16 + lr) * ROWB) + lc;
    #pragma unroll
    for (int n2 = 0; n2 < 2; n2++)
        boff[n2] = (uint32_t)((warp_n * 32 + n2 * 16 + lr) * ROWB) + lc;

    float acc[4][4][4];
    #pragma unroll
    for (int i = 0; i < 4; i++)
        #pragma unroll
        for (int j = 0; j < 4; j++)
            #pragma unroll
            for (int v = 0; v < 4; v++) acc[i][j][v] = 0.f;

    const int nk = K >> 5;
    load_stage(0, 0);
    CP_COMMIT();

    for (int t = 0; t < nk; t++) {
        if (t + 1 < nk) { load_stage((t + 1) & 1, (t + 1) << 5); CP_COMMIT(); CP_WAIT_1(); }
        else            { CP_WAIT_0(); }
        __syncthreads();

        const uint32_t s = sb + (t & 1) * STAGE_B;
        #pragma unroll
        for (int k16 = 0; k16 < 2; k16++) {
            const uint32_t kb = (uint32_t)(k16 * 32);
            uint32_t ah[4][4], al[4][4], bh[2][4], bl[2][4];
            #pragma unroll
            for (int mt = 0; mt < 4; mt++) ldsm4(ah[mt], s + OFF_AH + aoff[mt] + kb);
            #pragma unroll
            for (int n2 = 0; n2 < 2; n2++) ldsm4(bh[n2], s + OFF_BH + boff[n2] + kb);
            #pragma unroll
            for (int mt = 0; mt < 4; mt++)
                #pragma unroll
                for (int nt = 0; nt < 4; nt++) {
                    const uint32_t* b = bh[nt >> 1];
                    mma16816(acc[mt][nt], ah[mt][0], ah[mt][1], ah[mt][2], ah[mt][3],
                             (nt & 1) ? b[1] : b[0], (nt & 1) ? b[3] : b[2]);
                }
            #pragma unroll
            for (int n2 = 0; n2 < 2; n2++) ldsm4(bl[n2], s + OFF_BL + boff[n2] + kb);
            #pragma unroll
            for (int mt = 0; mt < 4; mt++)
                #pragma unroll
                for (int nt = 0; nt < 4; nt++) {
                    const uint32_t* b = bl[nt >> 1];
                    mma16816(acc[mt][nt], ah[mt][0], ah[mt][1], ah[mt][2], ah[mt][3],
                             (nt & 1) ? b[1] : b[0], (nt & 1) ? b[3] : b[2]);
                }
            #pragma unroll
            for (int mt = 0; mt < 4; mt++) ldsm4(al[mt], s + OFF_AL + aoff[mt] + kb);
            #pragma unroll
            for (int mt = 0; mt < 4; mt++)
                #pragma unroll
                for (int nt = 0; nt < 4; nt++) {
                    const uint32_t* b = bh[nt >> 1];
                    mma16816(acc[mt][nt], al[mt][0], al[mt][1], al[mt][2], al[mt][3],
                             (nt & 1) ? b[1] : b[0], (nt & 1) ? b[3] : b[2]);
                }
        }
        __syncthreads();
    }

    const int group = lane >> 2, tig = lane & 3;
    if (OUT_MODE == 2) {
        // per-row partial dots with wmu/wsg over this CTA's 128 cols
        float pmu[8], psg[8];
        #pragma unroll
        for (int i = 0; i < 8; i++) { pmu[i] = 0.f; psg[i] = 0.f; }
        #pragma unroll
        for (int mt = 0; mt < 4; mt++)
            #pragma unroll
            for (int nt = 0; nt < 4; nt++) {
                int c = bx * 128 + warp_n * 32 + nt * 8 + tig * 2;
                float w0m = wmu[c], w1m = wmu[c + 1];
                float w0s = wsg[c], w1s = wsg[c + 1];
                pmu[mt * 2 + 0] += acc[mt][nt][0] * w0m + acc[mt][nt][1] * w1m;
                pmu[mt * 2 + 1] += acc[mt][nt][2] * w0m + acc[mt][nt][3] * w1m;
                psg[mt * 2 + 0] += acc[mt][nt][0] * w0s + acc[mt][nt][1] * w1s;
                psg[mt * 2 + 1] += acc[mt][nt][2] * w0s + acc[mt][nt][3] * w1s;
            }
        #pragma unroll
        for (int o = 1; o <= 2; o <<= 1)
            #pragma unroll
            for (int i = 0; i < 8; i++) {
                pmu[i] += __shfl_xor_sync(0xffffffffu, pmu[i], o);
                psg[i] += __shfl_xor_sync(0xffffffffu, psg[i], o);
            }
        float* sp = (float*)dsm;          // [128][4][2]
        __syncthreads();
        if (tig == 0) {
            #pragma unroll
            for (int mt = 0; mt < 4; mt++) {
                int ra = warp_m * 64 + mt * 16 + group;
                sp[(ra * 4 + warp_n) * 2 + 0] = pmu[mt * 2 + 0];
                sp[(ra * 4 + warp_n) * 2 + 1] = psg[mt * 2 + 0];
                sp[((ra + 8) * 4 + warp_n) * 2 + 0] = pmu[mt * 2 + 1];
                sp[((ra + 8) * 4 + warp_n) * 2 + 1] = psg[mt * 2 + 1];
            }
        }
        __syncthreads();
        if (tid < 128) {
            float m = 0.f, g = 0.f;
            #pragma unroll
            for (int w = 0; w < 4; w++) {
                m += sp[(tid * 4 + w) * 2 + 0];
                g += sp[(tid * 4 + w) * 2 + 1];
            }
            long long ridx = ((long long)(bz * 16 + by) * 128 + tid);
            gpart[ridx * 16 + bx * 2 + 0] = m * alpha;
            gpart[ridx * 16 + bx * 2 + 1] = g * alpha;
        }
        return;
    }

    #pragma unroll
    for (int mt = 0; mt < 4; mt++) {
        #pragma unroll
        for (int nt = 0; nt < 4; nt++) {
            int row = by * 128 + warp_m * 64 + mt * 16 + group;
            int col = bx * 128 + warp_n * 32 + nt * 8 + tig * 2;
            float v0 = alpha * acc[mt][nt][0], v1 = alpha * acc[mt][nt][1];
            float v2 = alpha * acc[mt][nt][2], v3 = alpha * acc[mt][nt][3];
            if (OUT_MODE == 0) {
                float* p0 = C + (long long)bz * sC + (long long)row * ldc + col;
                float* p1 = p0 + 8LL * ldc;
                *(float2*)p0 = make_float2(v0, v1);
                *(float2*)p1 = make_float2(v2, v3);
            } else {
                long long o0 = (long long)bz * sC + (long long)row * ldc + col;
                long long o1 = o0 + 8LL * ldc;
                bf16 h0 = __float2bfloat16(v0), h1 = __float2bfloat16(v1);
                bf16 h2 = __float2bfloat16(v2), h3 = __float2bfloat16(v3);
                __nv_bfloat162 hh0 = {h0, h1}, hh1 = {h2, h3};
                __nv_bfloat162 ll0 = {__float2bfloat16(v0 - __bfloat162float(h0)),
                                      __float2bfloat16(v1 - __bfloat162float(h1))};
                __nv_bfloat162 ll1 = {__float2bfloat16(v2 - __bfloat162float(h2)),
                                      __float2bfloat16(v3 - __bfloat162float(h3))};
                *(__nv_bfloat162*)(Ch + o0) = hh0;
                *(__nv_bfloat162*)(Cl + o0) = ll0;
                *(__nv_bfloat162*)(Ch + o1) = hh1;
                *(__nv_bfloat162*)(Cl + o1) = ll1;
            }
        }
    }
}

// ------------------------- analytic-A GEMM (ctx = r · valT^T) --------------
// ctx[q][j] = sum_n r[q][n] * valT[j][n]; r synthesized from row params.
// M=128/CTA (by), N=128 (j), K=1024 (n), bz = h. B double-buffered cp.async.
static const int R_SMEM = 2 * (2 * TILE_B);   // 40960

__global__ __launch_bounds__(256, 1)
void gemm_r(const bf16* __restrict__ Bh, const bf16* __restrict__ Bl,
            const float* __restrict__ params,
            bf16* __restrict__ Ch, bf16* __restrict__ Cl)
{
    extern __shared__ char dsm[];
    const uint32_t sb = smem_u32(dsm);
    const int tid = threadIdx.x, lane = tid & 31, wid = tid >> 5;
    const int warp_m = wid >> 2, warp_n = wid & 3;
    const int by = blockIdx.y, bz = blockIdx.z;
    const int group = lane >> 2, tig = lane & 3;
    const float INV511 = 1.0f / 511.0f;

    const bf16* B0h = Bh + (long long)(bz * 128) * 1024;
    const bf16* B0l = Bl + (long long)(bz * 128) * 1024;

    // row params for this thread's 8 rows (4 m-tiles x {group, group+8})
    float mu_[8], c0_[8], h0_[8], c1_[8], h1_[8];
    {
        const long long pbase = (long long)(bz * 2048 + by * 128);
        #pragma unroll
        for (int mt = 0; mt < 4; mt++) {
            int ra = warp_m * 64 + mt * 16 + group;
            const float* p0 = params + (pbase + ra) * 8;
            const float* p1 = params + (pbase + ra + 8) * 8;
            mu_[mt*2+0] = p0[0]; c0_[mt*2+0] = p0[1]; h0_[mt*2+0] = p0[2];
            c1_[mt*2+0] = p0[3]; h1_[mt*2+0] = p0[4];
            mu_[mt*2+1] = p1[0]; c0_[mt*2+1] = p1[1]; h0_[mt*2+1] = p1[2];
            c1_[mt*2+1] = p1[3]; h1_[mt*2+1] = p1[4];
        }
    }

    // B stage: 2 planes x 128 rows x 4 chunks = 1024 chunks; 4 per thread
    auto load_stage = [&](int s, int k0) {
        uint32_t d = sb + s * (2 * TILE_B);
        #pragma unroll
        for (int j = 0; j < 4; j++) {
            int c = tid + j * 256;
            int plane = c >> 9, idx = c & 511;
            int row = idx >> 2, q4 = idx & 3;
            uint32_t dst = d + plane * TILE_B + (uint32_t)(row * ROWB + q4 * 16);
            const bf16* src = (plane ? B0l : B0h) + (long long)row * 1024 + k0 + q4 * 8;
            CP_ASYNC16(dst, src);
        }
    };

    const int lr = lane & 15;
    const uint32_t lc = (uint32_t)((lane >> 4) * 16);
    uint32_t boff[2];
    #pragma unroll
    for (int n2 = 0; n2 < 2; n2++)
        boff[n2] = (uint32_t)((warp_n * 32 + n2 * 16 + lr) * ROWB) + lc;

    float acc[4][4][4];
    #pragma unroll
    for (int i = 0; i < 4; i++)
        #pragma unroll
        for (int j = 0; j < 4; j++)
            #pragma unroll
            for (int v = 0; v < 4; v++) acc[i][j][v] = 0.f;

    load_stage(0, 0);
    CP_COMMIT();

    for (int t = 0; t < 32; t++) {
        if (t + 1 < 32) { load_stage((t + 1) & 1, (t + 1) << 5); CP_COMMIT(); CP_WAIT_1(); }
        else            { CP_WAIT_0(); }
        __syncthreads();

        const uint32_t s = sb + (t & 1) * (2 * TILE_B);
        #pragma unroll
        for (int k16 = 0; k16 < 2; k16++) {
            const int kb = t * 32 + k16 * 16;          // global n base
            const uint32_t kbb = (uint32_t)(k16 * 32);
            uint32_t bh[2][4], bl[2][4];
            #pragma unroll
            for (int n2 = 0; n2 < 2; n2++) {
                ldsm4(bh[n2], s + boff[n2] + kbb);
                ldsm4(bl[n2], s + TILE_B + boff[n2] + kbb);
            }
            const float bmu0 = (float)((kb >> 1) + tig) * INV511;
            const float bmu1 = bmu0 + 4.0f * INV511;
            #pragma unroll
            for (int mt = 0; mt < 4; mt++) {
                uint32_t ah[4], al[4];
                #pragma unroll
                for (int f = 0; f < 4; f++) {
                    const int i = mt * 2 + (f & 1);          // row slot
                    const float bm = (f < 2) ? bmu0 : bmu1;  // col block
                    float d = bm - mu_[i];
                    float t2 = d * d;
                    float ve = c0_[i] * __expf(h0_[i] * t2); // even col
                    float vo = c1_[i] * __expf(h1_[i] * t2); // odd col
                    bf16 he = __float2bfloat16(ve), ho = __float2bfloat16(vo);
                    __nv_bfloat162 hh = {he, ho};
                    __nv_bfloat162 ll = {__float2bfloat16(ve - __bfloat162float(he)),
                                         __float2bfloat16(vo - __bfloat162float(ho))};
                    ah[f] = *(uint32_t*)&hh;
                    al[f] = *(uint32_t*)&ll;
                }
                #pragma unroll
                for (int nt = 0; nt < 4; nt++) {
                    const uint32_t* b = bh[nt >> 1];
                    uint32_t b0 = (nt & 1) ? b[1] : b[0], b1 = (nt & 1) ? b[3] : b[2];
                    mma16816(acc[mt][nt], ah[0], ah[1], ah[2], ah[3], b0, b1);
                    const uint32_t* bb = bl[nt >> 1];
                    uint32_t c0b = (nt & 1) ? bb[1] : bb[0], c1b = (nt & 1) ? bb[3] : bb[2];
                    mma16816(acc[mt][nt], ah[0], ah[1], ah[2], ah[3], c0b, c1b);
                    mma16816(acc[mt][nt], al[0], al[1], al[2], al[3], b0, b1);
                }
            }
        }
        __syncthreads();
    }

    // epilogue: ctx split bf16, ldc = 2048, col offset h*128
    #pragma unroll
    for (int mt = 0; mt < 4; mt++) {
        #pragma unroll
        for (int nt = 0; nt < 4; nt++) {
            int row = by * 128 + warp_m * 64 + mt * 16 + group;
            int col = bz * 128 + warp_n * 32 + nt * 8 + tig * 2;
            long long o0 = (long long)row * 2048 + col;
            long long o1 = o0 + 8LL * 2048;
            float v0 = acc[mt][nt][0], v1 = acc[mt][nt][1];
            float v2 = acc[mt][nt][2], v3 = acc[mt][nt][3];
            bf16 h0 = __float2bfloat16(v0), h1 = __float2bfloat16(v1);
            bf16 h2 = __float2bfloat16(v2), h3 = __float2bfloat16(v3);
            __nv_bfloat162 hh0 = {h0, h1}, hh1 = {h2, h3};
            __nv_bfloat162 ll0 = {__float2bfloat16(v0 - __bfloat162float(h0)),
                                  __float2bfloat16(v1 - __bfloat162float(h1))};
            __nv_bfloat162 ll1 = {__float2bfloat16(v2 - __bfloat162float(h2)),
                                  __float2bfloat16(v3 - __bfloat162float(h3))};
            *(__nv_bfloat162*)(Ch + o0) = hh0;
            *(__nv_bfloat162*)(Cl + o0) = ll0;
            *(__nv_bfloat162*)(Ch + o1) = hh1;
            *(__nv_bfloat162*)(Cl + o1) = ll1;
        }
    }
}

// ------------------------- launch ------------------------------------------
extern "C" void kernel_launch(void* const* d_in, const int* in_sizes, int n_in,
                              void* d_out, int out_size)
{
    (void)in_sizes; (void)n_in; (void)out_size;
    const float* dk   = (const float*)d_in[0];
    const float* dq   = (const float*)d_in[1];
    const float* dWk  = (const float*)d_in[2];
    const float* dWv  = (const float*)d_in[3];
    const float* dWo  = (const float*)d_in[4];
    const float* dwmu = (const float*)d_in[5];
    const float* dwsg = (const float*)d_in[6];
    float* dout = (float*)d_out;

    compute_G2_host();

    bf16 *pWh, *pWl, *pkh, *pkl, *pqh, *pql, *pWoh, *pWol, *pG2h, *pG2l;
    bf16 *pKVth, *pKVtl, *pkeysh, *pkeysl, *pvalTh, *pvalTl;
    bf16 *pctxh, *pctxl;
    float *ppart, *pparams;
    cudaGetSymbolAddress((void**)&pWh,   g_Wh);   cudaGetSymbolAddress((void**)&pWl,   g_Wl);
    cudaGetSymbolAddress((void**)&pkh,   g_kh);   cudaGetSymbolAddress((void**)&pkl,   g_kl);
    cudaGetSymbolAddress((void**)&pqh,   g_qh);   cudaGetSymbolAddress((void**)&pql,   g_ql);
    cudaGetSymbolAddress((void**)&pWoh,  g_Woh);  cudaGetSymbolAddress((void**)&pWol,  g_Wol);
    cudaGetSymbolAddress((void**)&pG2h,  g_G2h);  cudaGetSymbolAddress((void**)&pG2l,  g_G2l);
    cudaGetSymbolAddress((void**)&pKVth, g_KVth); cudaGetSymbolAddress((void**)&pKVtl, g_KVtl);
    cudaGetSymbolAddress((void**)&pkeysh,g_keysh);cudaGetSymbolAddress((void**)&pkeysl,g_keysl);
    cudaGetSymbolAddress((void**)&pvalTh,g_valTh);cudaGetSymbolAddress((void**)&pvalTl,g_valTl);
    cudaGetSymbolAddress((void**)&pctxh, g_ctxh); cudaGetSymbolAddress((void**)&pctxl, g_ctxl);
    cudaGetSymbolAddress((void**)&ppart, g_part); cudaGetSymbolAddress((void**)&pparams, g_params);

    cudaFuncSetAttribute(mma_gemm<0>, cudaFuncAttributeMaxDynamicSharedMemorySize, SMEM_BYTES);
    cudaFuncSetAttribute(mma_gemm<1>, cudaFuncAttributeMaxDynamicSharedMemorySize, SMEM_BYTES);
    cudaFuncSetAttribute(mma_gemm<2>, cudaFuncAttributeMaxDynamicSharedMemorySize, SMEM_BYTES);
    cudaFuncSetAttribute(gemm_r,      cudaFuncAttributeMaxDynamicSharedMemorySize, R_SMEM);

    // splits of raw inputs
    {
        int n4;
        n4 = 2048 * 2048 / 4;
        split_kernel<<<(n4 + 255) / 256, 256>>>((const float4*)dWk, (uint2*)pWh, (uint2*)pWl, n4);
        split_kernel<<<(n4 + 255) / 256, 256>>>((const float4*)dWv,
                                                (uint2*)(pWh + 2048 * 2048), (uint2*)(pWl + 2048 * 2048), n4);
        split_kernel<<<(n4 + 255) / 256, 256>>>((const float4*)dWo, (uint2*)pWoh, (uint2*)pWol, n4);
        n4 = 512 * 2048 / 4;
        split_kernel<<<(n4 + 255) / 256, 256>>>((const float4*)dk, (uint2*)pkh, (uint2*)pkl, n4);
        n4 = 16 * 2048 * 128 / 4;
        split_kernel<<<(n4 + 255) / 256, 256>>>((const float4*)dq, (uint2*)pqh, (uint2*)pql, n4);
        int n16 = 1024 * 512 * 2 / 16;
        copy_g2_kernel<<<(n16 + 255) / 256, 256>>>((const uint4*)hG2h, (const uint4*)hG2l,
                                                   (uint4*)pG2h, (uint4*)pG2l, n16);
    }

    // 1: KVt[z*2048+j][l] = W[z][j]·k[l]     M=2048 N=512 K=2048, batch 2
    {
        dim3 g(4, 16, 2);
        mma_gemm<1><<<g, 256, SMEM_BYTES>>>(pWh, pWl, 2048, 2048LL * 2048,
                                            pkh, pkl, 2048, 0,
                                            nullptr, pKVth, pKVtl, 512, 2048LL * 512,
                                            2048, 1.0f, nullptr, nullptr, nullptr);
    }
    // 2a: keys[n][j] = G2[n]·KVt_key[j]      M=1024 N=2048 K=512
    {
        dim3 g(16, 8, 1);
        mma_gemm<1><<<g, 256, SMEM_BYTES>>>(pG2h, pG2l, 512, 0,
                                            pKVth, pKVtl, 512, 0,
                                            nullptr, pkeysh, pkeysl, 2048, 0,
                                            512, 1.0f, nullptr, nullptr, nullptr);
    }
    // 2b: valT[j][n] = KVt_val[j]·G2[n]      M=2048 N=1024 K=512
    {
        dim3 g(8, 16, 1);
        mma_gemm<1><<<g, 256, SMEM_BYTES>>>(pKVth + 2048LL * 512, pKVtl + 2048LL * 512, 512, 0,
                                            pG2h, pG2l, 512, 0,
                                            nullptr, pvalTh, pvalTl, 1024, 0,
                                            512, 1.0f, nullptr, nullptr, nullptr);
    }
    // 3: scores reduced in-register -> per-row partials (no S materialized)
    {
        dim3 g(8, 16, 16);
        mma_gemm<2><<<g, 256, SMEM_BYTES>>>(pqh, pql, 128, 2048LL * 128,
                                            pkeysh, pkeysl, 2048, 128,
                                            nullptr, nullptr, nullptr, 0, 0,
                                            128, 0.08838834764831845f, dwmu, dwsg, ppart);
    }
    // 4: fold partials -> row params
    reduce_params<<<128, 256>>>(ppart, pparams);

    // 5: ctx = r · valT^T with analytic A
    {
        dim3 g(1, 16, 16);
        gemm_r<<<g, 256, R_SMEM>>>(pvalTh, pvalTl, pparams, pctxh, pctxl);
    }
    // 6: out[q][o] = ctx[q]·Wo[o]            M=2048 N=2048 K=2048
    {
        dim3 g(16, 16, 1);
        mma_gemm<0><<<g, 256, SMEM_BYTES>>>(pctxh, pctxl, 2048, 0,
                                            pWoh, pWol, 2048, 0,
                                            dout, nullptr, nullptr, 2048, 0,
                                            2048, 1.0f, nullptr, nullptr, nullptr);
    }
}